// round 15
// baseline (speedup 1.0000x reference)
#include <cuda_runtime.h>
#include <cstdint>

// ============================================================================
// out[524288,128] = x @ P^T, P = Sinkhorn(exp(clip((logits+gumbel(u))/3)))
// Fused persistent kernel. FULLY WARP-INDEPENDENT pipelines (R14, proven):
//   - 512 threads = 16 warps; twin warps {w, w+8} process the SAME 32-row band
//   - per-warp private double-buffered 4 KB k-quarter slots (32x32, swizzled),
//     cp.async.cg + commit_group / wait_group 1; zero mainloop sync
//   R15 additions:
//   - prefetch.global.L2 of band b+NW at loop top: cp.async then sources from
//     L2 (~250cyc) instead of DRAM (~600-1000) -- depth-2 pipeline can cover L2
//   - PF repacked to float4: B-fragment loads = 4x LDS.128 per k-step instead
//     of 8x LDS.64 (same bytes, half the issue slots / LDS floor pressure)
// (tcgen05 unavailable: harness targets compute_103, not 103a.)
// ============================================================================

#define EPSF 1e-20f

__device__ __forceinline__ uint32_t smem_u32(const void* p) {
    uint32_t a;
    asm("{ .reg .u64 t; cvta.to.shared.u64 t, %1; cvt.u32.u64 %0, t; }" : "=r"(a) : "l"(p));
    return a;
}
__device__ __forceinline__ void cp16(float* dst, const float* src) {
    uint32_t d = smem_u32(dst);
    asm volatile("cp.async.cg.shared.global [%0], [%1], 16;" :: "r"(d), "l"(src) : "memory");
}
__device__ __forceinline__ void cp_commit() { asm volatile("cp.async.commit_group;" ::: "memory"); }
__device__ __forceinline__ void cp_wait1()  { asm volatile("cp.async.wait_group 1;" ::: "memory"); }

// smem plan: PF 16384 f | SLOTS 16 warps * 2 * 1024 f | Rv,Cv 256 f
static constexpr int PF_FLOATS   = 16384;
static constexpr int SLOT_FLOATS = 1024;                 // 32 rows x 32 cols
static constexpr int SLOTS_TOTAL = 16 * 2 * SLOT_FLOATS; // 32768
static constexpr int SMEM_BYTES  = (PF_FLOATS + SLOTS_TOTAL + 256) * 4;  // 197632

// swizzled float offset within a 32x32 slot: row 0..31, c4 = 16B chunk 0..7
__device__ __forceinline__ int soff(int row, int c4) {
    return row * 32 + (((c4) ^ (row & 7)) << 2);
}

__global__ void __launch_bounds__(512, 1)
fused_kernel(const float* __restrict__ x,
             const float* __restrict__ logits,
             const float* __restrict__ u,
             float* __restrict__ out, int nbands) {
    extern __shared__ float sh[];
    float*  PF    = sh;
    float*  SLOTS = sh + PF_FLOATS;
    float*  Rv    = SLOTS + SLOTS_TOTAL;   // 128
    float*  Cv    = Rv + 128;              // 128
    float4* PF4   = reinterpret_cast<float4*>(PF);

    const int tid  = threadIdx.x;
    const int lane = tid & 31;
    const int wid  = tid >> 5;
    const int wn   = wid >> 3;      // n-half: cols [wn*64, wn*64+64)

    float* SA = SLOTS + wid * 2 * SLOT_FLOATS;
    float* SB = SA + SLOT_FLOATS;

    // ================= sinkhorn prologue (proven 512-thread scheme) ==========
    {
        float* A = SLOTS;   // scratch (slots region, pre-mainloop)
        for (int idx = tid; idx < 16384; idx += 512) {
            float uv = u[idx];
            float g  = -logf(-logf(uv + EPSF) + EPSF);
            float la = (logits[idx] + g) * (1.0f / 3.0f);
            la = fminf(10.0f, fmaxf(-10.0f, la));
            A[idx] = expf(la);
        }
        if (tid < 128) Cv[tid] = 1.0f;
        __syncthreads();

        const int i = tid >> 2;   // row/col 0..127
        const int s = tid & 3;

        float4 a4[8];
        float  at[32];
#pragma unroll
        for (int k = 0; k < 8; k++)
            a4[k] = *reinterpret_cast<const float4*>(&A[i * 128 + k * 16 + s * 4]);
#pragma unroll
        for (int k = 0; k < 8; k++)
#pragma unroll
            for (int e = 0; e < 4; e++)
                at[k * 4 + e] = A[(k * 16 + s * 4 + e) * 128 + i];

        for (int it = 0; it < 20; it++) {
            float sum = 0.0f;
#pragma unroll
            for (int k = 0; k < 8; k++) {
                float4 cv = *reinterpret_cast<const float4*>(&Cv[k * 16 + s * 4]);
                sum += a4[k].x * cv.x + a4[k].y * cv.y + a4[k].z * cv.z + a4[k].w * cv.w;
            }
            sum += __shfl_xor_sync(0xffffffffu, sum, 1);
            sum += __shfl_xor_sync(0xffffffffu, sum, 2);
            if (s == 0) Rv[i] = 1.0f / sum;
            __syncthreads();

            float sum2 = 0.0f;
#pragma unroll
            for (int k = 0; k < 8; k++) {
                float4 rv = *reinterpret_cast<const float4*>(&Rv[k * 16 + s * 4]);
                sum2 += at[k * 4 + 0] * rv.x + at[k * 4 + 1] * rv.y +
                        at[k * 4 + 2] * rv.z + at[k * 4 + 3] * rv.w;
            }
            sum2 += __shfl_xor_sync(0xffffffffu, sum2, 1);
            sum2 += __shfl_xor_sync(0xffffffffu, sum2, 2);
            if (s == 0) Cv[i] = 1.0f / sum2;
            __syncthreads();
        }

        // P = diag(r) A diag(c) * (1+2^-11) [mma RZ-truncation compensation],
        // tf32-rounded, scattered into FLOAT4 B-fragment order:
        //   PF4[(ss*8 + (ntg>>1))*32 + (n&7)*4 + (ko&3)]
        //     element (ntg&1)*2 + (ko>>2), where ntg = n>>3, ss = k>>3, ko = k&7
        const float comp = 1.0f + 0.00048828125f;
        for (int idx = tid; idx < 16384; idx += 512) {
            int n = idx >> 7, k = idx & 127;
            float p = Rv[n] * A[n * 128 + k] * Cv[k] * comp;
            float pt32;
            asm("cvt.rna.tf32.f32 %0, %1;" : "=f"(pt32) : "f"(p));
            int ss = k >> 3, ko = k & 7, ntg = n >> 3;
            int fi = (((ss * 8 + (ntg >> 1)) * 32 + (n & 7) * 4 + (ko & 3)) << 2)
                     + ((ntg & 1) << 1) + (ko >> 2);
            PF[fi] = pt32;
        }
        __syncthreads();   // PF ready; slots free. LAST barrier of the kernel.
    }

    // ================= per-warp independent mainloop ==========================
    // twin warps {wid, wid+8} share the same band (R14 fix).
    const int NW = gridDim.x * 8;                        // bands per pass
    const int gw = blockIdx.x * 8 + (wid & 7);           // this warp's band
    if (gw >= nbands) return;

    // fill one k-quarter (32 rows x 32 cols) of band B into SLOT (8 cp16/thread)
#define ISSUE_Q(SLOT, B, KQ)                                                     \
    {                                                                            \
        const float* srcb = x + (size_t)(B) * 32 * 128 + (KQ) * 32;              \
        _Pragma("unroll")                                                        \
        for (int i = 0; i < 8; i++) {                                            \
            int f = i * 32 + lane;                                               \
            int row = f >> 3, c4 = f & 7;                                        \
            cp16((SLOT) + soff(row, c4), srcb + (size_t)row * 128 + c4 * 4);     \
        }                                                                        \
    }

// compute 4 k-steps of quarter KQ from SLOT into acc (B via LDS.128)
#define COMPUTE_Q(SLOT, KQ)                                                       \
        _Pragma("unroll")                                                         \
        for (int s4 = 0; s4 < 4; s4++) {                                          \
            int s = (KQ) * 4 + s4;                                                \
            float4 bq[4];                                                         \
            _Pragma("unroll")                                                     \
            for (int np = 0; np < 4; np++)                                        \
                bq[np] = PF4[(s * 8 + wn * 4 + np) * 32 + lane];                  \
            _Pragma("unroll")                                                     \
            for (int mf = 0; mf < 2; mf++) {                                      \
                int rq = mf * 16 + (lane >> 2);                                   \
                int w4 = lane & 3;                                                \
                int bc = s4 * 2;                                                  \
                uint32_t a0 = __float_as_uint((SLOT)[soff(rq,     bc    ) + w4]); \
                uint32_t a1 = __float_as_uint((SLOT)[soff(rq + 8, bc    ) + w4]); \
                uint32_t a2 = __float_as_uint((SLOT)[soff(rq,     bc + 1) + w4]); \
                uint32_t a3 = __float_as_uint((SLOT)[soff(rq + 8, bc + 1) + w4]); \
                _Pragma("unroll")                                                 \
                for (int np = 0; np < 4; np++) {                                  \
                    asm volatile(                                                 \
                        "mma.sync.aligned.m16n8k8.row.col.f32.tf32.tf32.f32 "     \
                        "{%0,%1,%2,%3}, {%4,%5,%6,%7}, {%8,%9}, {%0,%1,%2,%3};"   \
                        : "+f"(acc[mf][2*np][0]), "+f"(acc[mf][2*np][1]),         \
                          "+f"(acc[mf][2*np][2]), "+f"(acc[mf][2*np][3])          \
                        : "r"(a0), "r"(a1), "r"(a2), "r"(a3),                     \
                          "r"(__float_as_uint(bq[np].x)),                         \
                          "r"(__float_as_uint(bq[np].y)));                        \
                    asm volatile(                                                 \
                        "mma.sync.aligned.m16n8k8.row.col.f32.tf32.tf32.f32 "     \
                        "{%0,%1,%2,%3}, {%4,%5,%6,%7}, {%8,%9}, {%0,%1,%2,%3};"   \
                        : "+f"(acc[mf][2*np+1][0]), "+f"(acc[mf][2*np+1][1]),     \
                          "+f"(acc[mf][2*np+1][2]), "+f"(acc[mf][2*np+1][3])      \
                        : "r"(a0), "r"(a1), "r"(a2), "r"(a3),                     \
                          "r"(__float_as_uint(bq[np].z)),                         \
                          "r"(__float_as_uint(bq[np].w)));                        \
                }                                                                 \
            }                                                                     \
        }

    // prologue: fill band gw quarters 0,1 (one commit group each)
    ISSUE_Q(SA, gw, 0); cp_commit();
    ISSUE_Q(SB, gw, 1); cp_commit();

    for (int b = gw; b < nbands; b += NW) {
        const int  bn   = b + NW;
        const bool more = bn < nbands;

        // L2-prefetch next band (16 KB = 128 lines; 4 lines/lane) so the
        // cp.asyncs issued later this iteration hit L2 instead of DRAM.
        if (more) {
            const float* pfb = x + (size_t)bn * 32 * 128;
#pragma unroll
            for (int i = 0; i < 4; i++)
                asm volatile("prefetch.global.L2 [%0];"
                             :: "l"(pfb + (size_t)(lane * 4 + i) * 32));
        }

        float acc[2][8][4];
#pragma unroll
        for (int mf = 0; mf < 2; mf++)
#pragma unroll
            for (int nt = 0; nt < 8; nt++)
#pragma unroll
                for (int q = 0; q < 4; q++) acc[mf][nt][q] = 0.0f;

        cp_wait1();                 // q0 resident (q1 may be in flight)
        COMPUTE_Q(SA, 0)
        ISSUE_Q(SA, b, 2); cp_commit();

        cp_wait1();                 // q1 resident
        COMPUTE_Q(SB, 1)
        ISSUE_Q(SB, b, 3); cp_commit();

        cp_wait1();                 // q2 resident
        COMPUTE_Q(SA, 2)
        if (more) { ISSUE_Q(SA, bn, 0); }
        cp_commit();

        cp_wait1();                 // q3 resident
        COMPUTE_Q(SB, 3)
        if (more) { ISSUE_Q(SB, bn, 1); }
        cp_commit();

        // ---- epilogue: direct STG.64 (each quad = one 32B sector) ----
        float2* og = reinterpret_cast<float2*>(out) + (size_t)b * 32 * 64;
#pragma unroll
        for (int mf = 0; mf < 2; mf++) {
            int r0 = mf * 16 + (lane >> 2);
#pragma unroll
            for (int nt = 0; nt < 8; nt++) {
                int colp = wn * 32 + nt * 4 + (lane & 3);
                og[(size_t)r0 * 64 + colp]       = make_float2(acc[mf][nt][0], acc[mf][nt][1]);
                og[(size_t)(r0 + 8) * 64 + colp] = make_float2(acc[mf][nt][2], acc[mf][nt][3]);
            }
        }
    }
#undef ISSUE_Q
#undef COMPUTE_Q
}

// ---------------------------------------------------------------------------
extern "C" void kernel_launch(void* const* d_in, const int* in_sizes, int n_in,
                              void* d_out, int out_size) {
    const float* x      = (const float*)d_in[0];
    const float* logits = (const float*)d_in[1];
    const float* u      = (const float*)d_in[2];
    float*       out    = (float*)d_out;

    int dev = 0, sms = 148;
    cudaGetDevice(&dev);
    cudaDeviceGetAttribute(&sms, cudaDevAttrMultiProcessorCount, dev);

    cudaFuncSetAttribute(fused_kernel, cudaFuncAttributeMaxDynamicSharedMemorySize, SMEM_BYTES);

    int rows   = in_sizes[0] / 128;   // 524288
    int nbands = rows / 32;           // 16384
    fused_kernel<<<sms, 512, SMEM_BYTES>>>(x, logits, u, out, nbands);
}

// round 16
// speedup vs baseline: 1.1286x; 1.1286x over previous
#include <cuda_runtime.h>
#include <cstdint>

// ============================================================================
// out[524288,128] = x @ P^T, P = Sinkhorn(exp(clip((logits+gumbel(u))/3)))
// Fused persistent kernel. FULLY WARP-INDEPENDENT pipelines (R14, proven):
//   - 512 threads = 16 warps; twin warps {w, w+8} process the SAME 32-row band
//   - per-warp private double-buffered 4 KB k-quarter slots (32x32, swizzled),
//     cp.async.cg + commit_group / wait_group 1; zero mainloop sync
//   R16 (single delta vs R14): PF stored in float4 fragment order -- B loads
//   are 4x LDS.128 per k-step instead of 8x LDS.64 (same bytes & crossbar
//   phases, HALF the instructions on the LDS->MMA critical path).
//   R15's prefetch.global.L2 removed (it caused the 150us regression: L2 35.7
//   -> 44.4%, duplicated per-twin probes, issue -2%).
// (tcgen05 unavailable: harness targets compute_103, not 103a.)
// ============================================================================

#define EPSF 1e-20f

__device__ __forceinline__ uint32_t smem_u32(const void* p) {
    uint32_t a;
    asm("{ .reg .u64 t; cvta.to.shared.u64 t, %1; cvt.u32.u64 %0, t; }" : "=r"(a) : "l"(p));
    return a;
}
__device__ __forceinline__ void cp16(float* dst, const float* src) {
    uint32_t d = smem_u32(dst);
    asm volatile("cp.async.cg.shared.global [%0], [%1], 16;" :: "r"(d), "l"(src) : "memory");
}
__device__ __forceinline__ void cp_commit() { asm volatile("cp.async.commit_group;" ::: "memory"); }
__device__ __forceinline__ void cp_wait1()  { asm volatile("cp.async.wait_group 1;" ::: "memory"); }

// smem plan: PF 16384 f | SLOTS 16 warps * 2 * 1024 f | Rv,Cv 256 f
static constexpr int PF_FLOATS   = 16384;
static constexpr int SLOT_FLOATS = 1024;                 // 32 rows x 32 cols
static constexpr int SLOTS_TOTAL = 16 * 2 * SLOT_FLOATS; // 32768
static constexpr int SMEM_BYTES  = (PF_FLOATS + SLOTS_TOTAL + 256) * 4;  // 197632

// swizzled float offset within a 32x32 slot: row 0..31, c4 = 16B chunk 0..7
__device__ __forceinline__ int soff(int row, int c4) {
    return row * 32 + (((c4) ^ (row & 7)) << 2);
}

__global__ void __launch_bounds__(512, 1)
fused_kernel(const float* __restrict__ x,
             const float* __restrict__ logits,
             const float* __restrict__ u,
             float* __restrict__ out, int nbands) {
    extern __shared__ float sh[];
    float*  PF    = sh;
    float*  SLOTS = sh + PF_FLOATS;
    float*  Rv    = SLOTS + SLOTS_TOTAL;   // 128
    float*  Cv    = Rv + 128;              // 128
    float4* PF4   = reinterpret_cast<float4*>(PF);

    const int tid  = threadIdx.x;
    const int lane = tid & 31;
    const int wid  = tid >> 5;
    const int wn   = wid >> 3;      // n-half: cols [wn*64, wn*64+64)

    float* SA = SLOTS + wid * 2 * SLOT_FLOATS;
    float* SB = SA + SLOT_FLOATS;

    // ================= sinkhorn prologue (proven 512-thread scheme) ==========
    {
        float* A = SLOTS;   // scratch (slots region, pre-mainloop)
        for (int idx = tid; idx < 16384; idx += 512) {
            float uv = u[idx];
            float g  = -logf(-logf(uv + EPSF) + EPSF);
            float la = (logits[idx] + g) * (1.0f / 3.0f);
            la = fminf(10.0f, fmaxf(-10.0f, la));
            A[idx] = expf(la);
        }
        if (tid < 128) Cv[tid] = 1.0f;
        __syncthreads();

        const int i = tid >> 2;   // row/col 0..127
        const int s = tid & 3;

        float4 a4[8];
        float  at[32];
#pragma unroll
        for (int k = 0; k < 8; k++)
            a4[k] = *reinterpret_cast<const float4*>(&A[i * 128 + k * 16 + s * 4]);
#pragma unroll
        for (int k = 0; k < 8; k++)
#pragma unroll
            for (int e = 0; e < 4; e++)
                at[k * 4 + e] = A[(k * 16 + s * 4 + e) * 128 + i];

        for (int it = 0; it < 20; it++) {
            float sum = 0.0f;
#pragma unroll
            for (int k = 0; k < 8; k++) {
                float4 cv = *reinterpret_cast<const float4*>(&Cv[k * 16 + s * 4]);
                sum += a4[k].x * cv.x + a4[k].y * cv.y + a4[k].z * cv.z + a4[k].w * cv.w;
            }
            sum += __shfl_xor_sync(0xffffffffu, sum, 1);
            sum += __shfl_xor_sync(0xffffffffu, sum, 2);
            if (s == 0) Rv[i] = 1.0f / sum;
            __syncthreads();

            float sum2 = 0.0f;
#pragma unroll
            for (int k = 0; k < 8; k++) {
                float4 rv = *reinterpret_cast<const float4*>(&Rv[k * 16 + s * 4]);
                sum2 += at[k * 4 + 0] * rv.x + at[k * 4 + 1] * rv.y +
                        at[k * 4 + 2] * rv.z + at[k * 4 + 3] * rv.w;
            }
            sum2 += __shfl_xor_sync(0xffffffffu, sum2, 1);
            sum2 += __shfl_xor_sync(0xffffffffu, sum2, 2);
            if (s == 0) Cv[i] = 1.0f / sum2;
            __syncthreads();
        }

        // P = diag(r) A diag(c) * (1+2^-11) [mma RZ-truncation compensation],
        // tf32-rounded, scattered into FLOAT4 B-fragment order:
        //   PF4[(ss*8 + (ntg>>1))*32 + (n&7)*4 + (ko&3)]
        //     element (ntg&1)*2 + (ko>>2);  ntg = n>>3, ss = k>>3, ko = k&7
        const float comp = 1.0f + 0.00048828125f;
        for (int idx = tid; idx < 16384; idx += 512) {
            int n = idx >> 7, k = idx & 127;
            float p = Rv[n] * A[n * 128 + k] * Cv[k] * comp;
            float pt32;
            asm("cvt.rna.tf32.f32 %0, %1;" : "=f"(pt32) : "f"(p));
            int ss = k >> 3, ko = k & 7, ntg = n >> 3;
            int fi = (((ss * 8 + (ntg >> 1)) * 32 + (n & 7) * 4 + (ko & 3)) << 2)
                     + ((ntg & 1) << 1) + (ko >> 2);
            PF[fi] = pt32;
        }
        __syncthreads();   // PF ready; slots free. LAST barrier of the kernel.
    }

    // ================= per-warp independent mainloop ==========================
    // twin warps {wid, wid+8} share the same band (R14 fix).
    const int NW = gridDim.x * 8;                        // bands per pass
    const int gw = blockIdx.x * 8 + (wid & 7);           // this warp's band
    if (gw >= nbands) return;

    // fill one k-quarter (32 rows x 32 cols) of band B into SLOT (8 cp16/thread)
#define ISSUE_Q(SLOT, B, KQ)                                                     \
    {                                                                            \
        const float* srcb = x + (size_t)(B) * 32 * 128 + (KQ) * 32;              \
        _Pragma("unroll")                                                        \
        for (int i = 0; i < 8; i++) {                                            \
            int f = i * 32 + lane;                                               \
            int row = f >> 3, c4 = f & 7;                                        \
            cp16((SLOT) + soff(row, c4), srcb + (size_t)row * 128 + c4 * 4);     \
        }                                                                        \
    }

// compute 4 k-steps of quarter KQ from SLOT into acc (B via LDS.128)
#define COMPUTE_Q(SLOT, KQ)                                                       \
        _Pragma("unroll")                                                         \
        for (int s4 = 0; s4 < 4; s4++) {                                          \
            int s = (KQ) * 4 + s4;                                                \
            float4 bq[4];                                                         \
            _Pragma("unroll")                                                     \
            for (int np = 0; np < 4; np++)                                        \
                bq[np] = PF4[(s * 8 + wn * 4 + np) * 32 + lane];                  \
            _Pragma("unroll")                                                     \
            for (int mf = 0; mf < 2; mf++) {                                      \
                int rq = mf * 16 + (lane >> 2);                                   \
                int w4 = lane & 3;                                                \
                int bc = s4 * 2;                                                  \
                uint32_t a0 = __float_as_uint((SLOT)[soff(rq,     bc    ) + w4]); \
                uint32_t a1 = __float_as_uint((SLOT)[soff(rq + 8, bc    ) + w4]); \
                uint32_t a2 = __float_as_uint((SLOT)[soff(rq,     bc + 1) + w4]); \
                uint32_t a3 = __float_as_uint((SLOT)[soff(rq + 8, bc + 1) + w4]); \
                _Pragma("unroll")                                                 \
                for (int np = 0; np < 4; np++) {                                  \
                    asm volatile(                                                 \
                        "mma.sync.aligned.m16n8k8.row.col.f32.tf32.tf32.f32 "     \
                        "{%0,%1,%2,%3}, {%4,%5,%6,%7}, {%8,%9}, {%0,%1,%2,%3};"   \
                        : "+f"(acc[mf][2*np][0]), "+f"(acc[mf][2*np][1]),         \
                          "+f"(acc[mf][2*np][2]), "+f"(acc[mf][2*np][3])          \
                        : "r"(a0), "r"(a1), "r"(a2), "r"(a3),                     \
                          "r"(__float_as_uint(bq[np].x)),                         \
                          "r"(__float_as_uint(bq[np].y)));                        \
                    asm volatile(                                                 \
                        "mma.sync.aligned.m16n8k8.row.col.f32.tf32.tf32.f32 "     \
                        "{%0,%1,%2,%3}, {%4,%5,%6,%7}, {%8,%9}, {%0,%1,%2,%3};"   \
                        : "+f"(acc[mf][2*np+1][0]), "+f"(acc[mf][2*np+1][1]),     \
                          "+f"(acc[mf][2*np+1][2]), "+f"(acc[mf][2*np+1][3])      \
                        : "r"(a0), "r"(a1), "r"(a2), "r"(a3),                     \
                          "r"(__float_as_uint(bq[np].z)),                         \
                          "r"(__float_as_uint(bq[np].w)));                        \
                }                                                                 \
            }                                                                     \
        }

    // prologue: fill band gw quarters 0,1 (one commit group each)
    ISSUE_Q(SA, gw, 0); cp_commit();
    ISSUE_Q(SB, gw, 1); cp_commit();

    for (int b = gw; b < nbands; b += NW) {
        const int  bn   = b + NW;
        const bool more = bn < nbands;

        float acc[2][8][4];
#pragma unroll
        for (int mf = 0; mf < 2; mf++)
#pragma unroll
            for (int nt = 0; nt < 8; nt++)
#pragma unroll
                for (int q = 0; q < 4; q++) acc[mf][nt][q] = 0.0f;

        cp_wait1();                 // q0 resident (q1 may be in flight)
        COMPUTE_Q(SA, 0)
        ISSUE_Q(SA, b, 2); cp_commit();

        cp_wait1();                 // q1 resident
        COMPUTE_Q(SB, 1)
        ISSUE_Q(SB, b, 3); cp_commit();

        cp_wait1();                 // q2 resident
        COMPUTE_Q(SA, 2)
        if (more) { ISSUE_Q(SA, bn, 0); }
        cp_commit();

        cp_wait1();                 // q3 resident
        COMPUTE_Q(SB, 3)
        if (more) { ISSUE_Q(SB, bn, 1); }
        cp_commit();

        // ---- epilogue: direct STG.64 (each quad = one 32B sector) ----
        float2* og = reinterpret_cast<float2*>(out) + (size_t)b * 32 * 64;
#pragma unroll
        for (int mf = 0; mf < 2; mf++) {
            int r0 = mf * 16 + (lane >> 2);
#pragma unroll
            for (int nt = 0; nt < 8; nt++) {
                int colp = wn * 32 + nt * 4 + (lane & 3);
                og[(size_t)r0 * 64 + colp]       = make_float2(acc[mf][nt][0], acc[mf][nt][1]);
                og[(size_t)(r0 + 8) * 64 + colp] = make_float2(acc[mf][nt][2], acc[mf][nt][3]);
            }
        }
    }
#undef ISSUE_Q
#undef COMPUTE_Q
}

// ---------------------------------------------------------------------------
extern "C" void kernel_launch(void* const* d_in, const int* in_sizes, int n_in,
                              void* d_out, int out_size) {
    const float* x      = (const float*)d_in[0];
    const float* logits = (const float*)d_in[1];
    const float* u      = (const float*)d_in[2];
    float*       out    = (float*)d_out;

    int dev = 0, sms = 148;
    cudaGetDevice(&dev);
    cudaDeviceGetAttribute(&sms, cudaDevAttrMultiProcessorCount, dev);

    cudaFuncSetAttribute(fused_kernel, cudaFuncAttributeMaxDynamicSharedMemorySize, SMEM_BYTES);

    int rows   = in_sizes[0] / 128;   // 524288
    int nbands = rows / 32;           // 16384
    fused_kernel<<<sms, 512, SMEM_BYTES>>>(x, logits, u, out, nbands);
}